// round 13
// baseline (speedup 1.0000x reference)
#include <cuda_runtime.h>
#include <cuda_fp16.h>
#include <cstdint>

// ---------------- problem constants ----------------
#define MROWS 8192          // B*S = 4*2048
#define KDIM  2048
#define NCOLS 6144          // 3*D fused QKV
#define LN_EPS 1e-5f

// ---------------- GEMM tiling ----------------
#define BM 128
#define BN 128
#define BK 64
#define NKT (KDIM / BK)     // 32 k-chunks per tile
#define NSTAGE 3
#define NTILES ((MROWS / BM) * (NCOLS / BN))   // 3072
#define NCTA   304                              // 152 SMs x 2 CTAs (GB300)

#define A_TILE_BYTES 16384          // 128 rows x 128B
#define B_TILE_BYTES 16384          // 128 rows x 128B
#define STAGE_BYTES  (A_TILE_BYTES + B_TILE_BYTES)   // 32768
#define GEMM_SMEM    (NSTAGE * STAGE_BYTES)          // 98304 -> 2 CTAs/SM

// ---------------- scratch (static device memory: allowed) ----------------
__device__ __half g_A[(size_t)MROWS * KDIM];   // 32 MB
__device__ __half g_W[(size_t)NCOLS * KDIM];   // 24 MB
__device__ float  g_bias[NCOLS];

// ---------------- helpers ----------------
__device__ __forceinline__ uint32_t smem_u32(const void* p) {
    return (uint32_t)__cvta_generic_to_shared(p);
}
__device__ __forceinline__ uint32_t swz128(uint32_t b) {
    return b ^ ((b >> 3) & 0x70);
}
__device__ __forceinline__ void cp16(uint32_t dst, const void* src) {
    asm volatile("cp.async.cg.shared.global [%0], [%1], 16;\n"
                 :: "r"(dst), "l"(src) : "memory");
}
__device__ __forceinline__ void cp_commit() {
    asm volatile("cp.async.commit_group;" ::: "memory");
}
__device__ __forceinline__ void ldsm_x4(uint32_t addr, uint32_t r[4]) {
    asm volatile("ldmatrix.sync.aligned.m8n8.x4.shared.b16 {%0,%1,%2,%3}, [%4];"
                 : "=r"(r[0]), "=r"(r[1]), "=r"(r[2]), "=r"(r[3]) : "r"(addr));
}
__device__ __forceinline__ void mma_f16(float c[4], const uint32_t a[4],
                                        const uint32_t b0, const uint32_t b1) {
    asm volatile(
        "mma.sync.aligned.m16n8k16.row.col.f32.f16.f16.f32 "
        "{%0,%1,%2,%3}, {%4,%5,%6,%7}, {%8,%9}, {%0,%1,%2,%3};"
        : "+f"(c[0]), "+f"(c[1]), "+f"(c[2]), "+f"(c[3])
        : "r"(a[0]), "r"(a[1]), "r"(a[2]), "r"(a[3]), "r"(b0), "r"(b1));
}
__device__ __forceinline__ uint32_t pack2h(float a, float b) {
    __half2 p = __halves2half2(__float2half_rn(a), __float2half_rn(b));
    return *reinterpret_cast<uint32_t*>(&p);
}

// tile id -> (m0, n0) with group-of-8 m-tile swizzle for L2 reuse
__device__ __forceinline__ void tile_coords(int t, int& m0, int& n0) {
    const int NT = NCOLS / BN;              // 48
    const int GM = 8;
    const int grp = t / (GM * NT);
    const int rem = t % (GM * NT);
    m0 = (grp * GM + (rem % GM)) * BM;
    n0 = (rem / GM) * BN;
}

// ====================================================================
// Kernel 1: fused prep.
//   blocks [0, MROWS):              LayerNorm row -> fp16 g_A
//   blocks [MROWS, MROWS+NCOLS):    weight row fp32->fp16 g_W + bias
// ====================================================================
__global__ __launch_bounds__(256) void prep_kernel(
    const float* __restrict__ x, const float* __restrict__ nw,
    const float* __restrict__ nb,
    const float* __restrict__ qw, const float* __restrict__ kw,
    const float* __restrict__ vw, const float* __restrict__ qb,
    const float* __restrict__ kb, const float* __restrict__ vb)
{
    const int tid = threadIdx.x;

    if (blockIdx.x >= MROWS) {
        // ---- weight convert path ----
        const int n = blockIdx.x - MROWS;
        const float* src;
        if (n < 2048) {
            src = qw + (size_t)n * KDIM;
            if (tid == 0) g_bias[n] = qb[n];
        } else if (n < 4096) {
            src = kw + (size_t)(n - 2048) * KDIM;
            if (tid == 0) g_bias[n] = kb[n - 2048];
        } else {
            src = vw + (size_t)(n - 4096) * KDIM;
            if (tid == 0) g_bias[n] = vb[n - 4096];
        }
        const float4* sr = reinterpret_cast<const float4*>(src);
        uint4* rowp = reinterpret_cast<uint4*>(g_W + (size_t)n * KDIM);
        const float4 a = sr[2 * tid];
        const float4 b = sr[2 * tid + 1];
        uint4 u;
        u.x = pack2h(a.x, a.y); u.y = pack2h(a.z, a.w);
        u.z = pack2h(b.x, b.y); u.w = pack2h(b.z, b.w);
        rowp[tid] = u;
        return;
    }

    // ---- LayerNorm path ----
    const int row = blockIdx.x;
    const float4* xr = reinterpret_cast<const float4*>(x + (size_t)row * KDIM);

    float4 v0 = xr[2 * tid];
    float4 v1 = xr[2 * tid + 1];

    float s = v0.x + v0.y + v0.z + v0.w + v1.x + v1.y + v1.z + v1.w;
    float q = v0.x*v0.x + v0.y*v0.y + v0.z*v0.z + v0.w*v0.w +
              v1.x*v1.x + v1.y*v1.y + v1.z*v1.z + v1.w*v1.w;

    #pragma unroll
    for (int o = 16; o > 0; o >>= 1) {
        s += __shfl_xor_sync(0xffffffffu, s, o);
        q += __shfl_xor_sync(0xffffffffu, q, o);
    }

    __shared__ float red[2][8];
    __shared__ float mu_s, rs_s;
    const int wid = tid >> 5, lane = tid & 31;
    if (lane == 0) { red[0][wid] = s; red[1][wid] = q; }
    __syncthreads();
    if (tid == 0) {
        float ss = 0.f, qq = 0.f;
        #pragma unroll
        for (int i = 0; i < 8; i++) { ss += red[0][i]; qq += red[1][i]; }
        float mu  = ss * (1.0f / KDIM);
        float var = qq * (1.0f / KDIM) - mu * mu;
        mu_s = mu;
        rs_s = rsqrtf(var + LN_EPS);
    }
    __syncthreads();
    const float mu = mu_s, rs = rs_s;

    const float4* wr = reinterpret_cast<const float4*>(nw);
    const float4* br = reinterpret_cast<const float4*>(nb);
    uint4* rowp = reinterpret_cast<uint4*>(g_A + (size_t)row * KDIM);

    const float4 w0 = wr[2 * tid], w1 = wr[2 * tid + 1];
    const float4 b0 = br[2 * tid], b1 = br[2 * tid + 1];
    uint4 u;
    u.x = pack2h((v0.x - mu) * rs * w0.x + b0.x, (v0.y - mu) * rs * w0.y + b0.y);
    u.y = pack2h((v0.z - mu) * rs * w0.z + b0.z, (v0.w - mu) * rs * w0.w + b0.w);
    u.z = pack2h((v1.x - mu) * rs * w1.x + b1.x, (v1.y - mu) * rs * w1.y + b1.y);
    u.w = pack2h((v1.z - mu) * rs * w1.z + b1.z, (v1.w - mu) * rs * w1.w + b1.w);
    rowp[tid] = u;
}

// ====================================================================
// Kernel 2: persistent fp16 mma.sync GEMM.
//   304 CTAs, each loops over tiles t = bid, bid+304, ...
//   The cp.async chunk stream crosses tile boundaries without draining:
//   prefetch pointers roll to the next tile 2 iterations early, so the
//   per-tile epilogue overlaps the next tile's loads.  R9-proven
//   iteration body (B-batch, A-batch, MMA block) unchanged.
// ====================================================================
__global__ __launch_bounds__(256, 2)
void qkv_gemm_kernel(float* __restrict__ out)
{
    extern __shared__ char smem[];
    const int tid  = threadIdx.x;
    const int wid  = tid >> 5;
    const int lane = tid & 31;
    const int wm   = wid & 1;       // 0..1  (64 rows each)
    const int wn   = wid >> 1;      // 0..3  (32 cols each)
    const uint32_t sbase = smem_u32(smem);
    const uint32_t send  = sbase + NSTAGE * STAGE_BYTES;

    // per-thread cp.async dest offsets (4 rows x 16B each for A and B)
    const int cr = tid >> 3;                 // row   0..31 (base)
    const int cc = tid & 7;                  // 16B col 0..7
    const uint32_t coff[4] = {
        swz128((uint32_t)((cr +  0) * 128 + cc * 16)),
        swz128((uint32_t)((cr + 32) * 128 + cc * 16)),
        swz128((uint32_t)((cr + 64) * 128 + cc * 16)),
        swz128((uint32_t)((cr + 96) * 128 + cc * 16)),
    };

    // prefetch-stream state
    int tp = blockIdx.x;                     // tile being prefetched
    int pm0, pn0;
    tile_coords(tp, pm0, pn0);
    const __half* pAg = g_A + (size_t)pm0 * KDIM;
    const __half* pWg = g_W + (size_t)pn0 * KDIM;
    int pk = 0;                              // k-offset of next chunk to load

    auto load_chunk = [&](uint32_t st) {
        #pragma unroll
        for (int j = 0; j < 4; j++)
            cp16(st + coff[j], pAg + (size_t)(cr + 32 * j) * KDIM + pk + cc * 8);
        #pragma unroll
        for (int j = 0; j < 4; j++)
            cp16(st + A_TILE_BYTES + coff[j],
                 pWg + (size_t)(cr + 32 * j) * KDIM + pk + cc * 8);
        cp_commit();
    };

    float acc[4][4][4];
    #pragma unroll
    for (int i = 0; i < 4; i++)
        #pragma unroll
        for (int j = 0; j < 4; j++)
            #pragma unroll
            for (int c = 0; c < 4; c++) acc[i][j][c] = 0.f;

    // prologue: chunks 0,1 of first tile
    load_chunk(sbase);               pk += BK;
    load_chunk(sbase + STAGE_BYTES); pk += BK;

    // precomputed lane pieces for ldmatrix addressing
    const int a_row_lane = lane & 15;                        // row within m16
    const int a_k_lane   = (lane >> 4) * 8;                  // k half
    const int b_row_lane = (lane & 7) + ((lane >> 4) << 3);  // row within n16
    const int b_k_lane   = ((lane >> 3) & 1) * 8;            // k half

    uint32_t stRead  = sbase;
    uint32_t stWrite = sbase + 2 * STAGE_BYTES;

    const int gid = lane >> 2;       // 0..7 row within m8 (epilogue)
    const int tq  = lane & 3;        // col pair           (epilogue)

    #pragma unroll 1
    for (int t = blockIdx.x; t < NTILES; t += NCTA) {
        #pragma unroll 1
        for (int kt = 0; kt < NKT; kt++) {
            // 1 commit + wait<=1 per iteration keeps the stream invariant
            asm volatile("cp.async.wait_group 1;" ::: "memory");
            __syncthreads();

            // roll prefetch stream: advance to next tile when k wraps
            if (pk == KDIM) {
                pk = 0;
                tp += NCTA;
                if (tp < NTILES) {
                    tile_coords(tp, pm0, pn0);
                    pAg = g_A + (size_t)pm0 * KDIM;
                    pWg = g_W + (size_t)pn0 * KDIM;
                }
            }
            if (tp < NTILES) load_chunk(stWrite);
            else             cp_commit();   // empty group: keeps count aligned
            pk += BK;

            const uint32_t aBase = stRead;
            const uint32_t bBase = stRead + A_TILE_BYTES;

            #pragma unroll
            for (int ks = 0; ks < 4; ks++) {
                const int k0 = ks * 16;
                // B fragments first
                uint32_t bf[4][2];
                #pragma unroll
                for (int p = 0; p < 2; p++) {
                    const int rown = wn * 32 + p * 16 + b_row_lane;
                    const uint32_t addr =
                        bBase + swz128((uint32_t)(rown * 128 + (k0 + b_k_lane) * 2));
                    uint32_t r[4];
                    ldsm_x4(addr, r);
                    bf[2*p][0] = r[0]; bf[2*p][1] = r[1];
                    bf[2*p+1][0] = r[2]; bf[2*p+1][1] = r[3];
                }
                uint32_t af[4][4];
                #pragma unroll
                for (int mt = 0; mt < 4; mt++) {
                    const int row = wm * 64 + mt * 16 + a_row_lane;
                    const uint32_t addr =
                        aBase + swz128((uint32_t)(row * 128 + (k0 + a_k_lane) * 2));
                    ldsm_x4(addr, af[mt]);
                }
                #pragma unroll
                for (int mt = 0; mt < 4; mt++)
                    #pragma unroll
                    for (int nt = 0; nt < 4; nt++)
                        mma_f16(acc[mt][nt], af[mt], bf[nt][0], bf[nt][1]);
            }

            // rotate stage pointers (wrap at NSTAGE)
            stRead  += STAGE_BYTES;  if (stRead  == send) stRead  = sbase;
            stWrite += STAGE_BYTES;  if (stWrite == send) stWrite = sbase;
        }

        // ---- epilogue for tile t (overlaps next tile's in-flight loads) ----
        int m0, n0;
        tile_coords(t, m0, n0);
        #pragma unroll
        for (int mt = 0; mt < 4; mt++) {
            const int row = m0 + wm * 64 + mt * 16 + gid;
            #pragma unroll
            for (int nt = 0; nt < 4; nt++) {
                const int col = n0 + wn * 32 + nt * 8 + tq * 2;
                const float bx = g_bias[col];
                const float by = g_bias[col + 1];
                float2 v0, v1;
                v0.x = acc[mt][nt][0] + bx;
                v0.y = acc[mt][nt][1] + by;
                v1.x = acc[mt][nt][2] + bx;
                v1.y = acc[mt][nt][3] + by;
                *reinterpret_cast<float2*>(out + (size_t)row * NCOLS + col) = v0;
                *reinterpret_cast<float2*>(out + (size_t)(row + 8) * NCOLS + col) = v1;
                acc[mt][nt][0] = 0.f; acc[mt][nt][1] = 0.f;
                acc[mt][nt][2] = 0.f; acc[mt][nt][3] = 0.f;
            }
        }
    }
}

// ====================================================================
// launch
// ====================================================================
extern "C" void kernel_launch(void* const* d_in, const int* in_sizes, int n_in,
                              void* d_out, int out_size)
{
    const float* x  = (const float*)d_in[0];
    const float* nw = (const float*)d_in[1];
    const float* nb = (const float*)d_in[2];
    const float* qw = (const float*)d_in[3];
    const float* qb = (const float*)d_in[4];
    const float* kw = (const float*)d_in[5];
    const float* kb = (const float*)d_in[6];
    const float* vw = (const float*)d_in[7];
    const float* vb = (const float*)d_in[8];
    float* out = (float*)d_out;

    cudaFuncSetAttribute(qkv_gemm_kernel,
                         cudaFuncAttributeMaxDynamicSharedMemorySize, GEMM_SMEM);

    prep_kernel<<<MROWS + NCOLS, 256>>>(x, nw, nb, qw, kw, vw, qb, kb, vb);
    qkv_gemm_kernel<<<NCTA, 256, GEMM_SMEM>>>(out);
}

// round 14
// speedup vs baseline: 1.0421x; 1.0421x over previous
#include <cuda_runtime.h>
#include <cuda_fp16.h>
#include <cuda.h>
#include <cstdint>

// ---------------- problem constants ----------------
#define MROWS 8192          // B*S = 4*2048
#define KDIM  2048
#define NCOLS 6144          // 3*D fused QKV
#define LN_EPS 1e-5f

// ---------------- GEMM tiling ----------------
#define BM 128
#define BN 128
#define BK 64
#define NKT (KDIM / BK)     // 32 k-chunks
#define NSTAGE 3

#define A_TILE_BYTES 16384          // 128 rows x 128B
#define B_TILE_BYTES 16384          // 128 rows x 128B
#define STAGE_BYTES  (A_TILE_BYTES + B_TILE_BYTES)   // 32768
#define GEMM_SMEM    (NSTAGE * STAGE_BYTES + 1024)   // +1024 for alignment

// ---------------- scratch (static device memory: allowed) ----------------
__device__ __half g_A[(size_t)MROWS * KDIM];   // 32 MB
__device__ __half g_W[(size_t)NCOLS * KDIM];   // 24 MB
__device__ float  g_bias[NCOLS];

// ---------------- helpers ----------------
__device__ __forceinline__ uint32_t smem_u32(const void* p) {
    return (uint32_t)__cvta_generic_to_shared(p);
}
__device__ __forceinline__ uint32_t swz128(uint32_t b) {
    return b ^ ((b >> 3) & 0x70);
}
__device__ __forceinline__ void ldsm_x4(uint32_t addr, uint32_t r[4]) {
    asm volatile("ldmatrix.sync.aligned.m8n8.x4.shared.b16 {%0,%1,%2,%3}, [%4];"
                 : "=r"(r[0]), "=r"(r[1]), "=r"(r[2]), "=r"(r[3]) : "r"(addr));
}
__device__ __forceinline__ void mma_f16(float c[4], const uint32_t a[4],
                                        const uint32_t b0, const uint32_t b1) {
    asm volatile(
        "mma.sync.aligned.m16n8k16.row.col.f32.f16.f16.f32 "
        "{%0,%1,%2,%3}, {%4,%5,%6,%7}, {%8,%9}, {%0,%1,%2,%3};"
        : "+f"(c[0]), "+f"(c[1]), "+f"(c[2]), "+f"(c[3])
        : "r"(a[0]), "r"(a[1]), "r"(a[2]), "r"(a[3]), "r"(b0), "r"(b1));
}
__device__ __forceinline__ uint32_t pack2h(float a, float b) {
    __half2 p = __halves2half2(__float2half_rn(a), __float2half_rn(b));
    return *reinterpret_cast<uint32_t*>(&p);
}
// ---- TMA / mbarrier (base sm_90 PTX features, not arch-conditional) ----
__device__ __forceinline__ void mbar_init(uint32_t mbar, uint32_t cnt) {
    asm volatile("mbarrier.init.shared.b64 [%0], %1;" :: "r"(mbar), "r"(cnt) : "memory");
}
__device__ __forceinline__ void mbar_expect_tx(uint32_t mbar, uint32_t bytes) {
    asm volatile("mbarrier.arrive.expect_tx.shared.b64 _, [%0], %1;"
                 :: "r"(mbar), "r"(bytes) : "memory");
}
__device__ __forceinline__ void mbar_wait(uint32_t mbar, uint32_t parity) {
    asm volatile(
        "{\n\t.reg .pred P1;\n\t"
        "WAIT_%=:\n\t"
        "mbarrier.try_wait.parity.acquire.cta.shared::cta.b64 P1, [%0], %1, 0x989680;\n\t"
        "@P1 bra.uni DONE_%=;\n\t"
        "bra.uni WAIT_%=;\n\t"
        "DONE_%=:\n\t}"
        :: "r"(mbar), "r"(parity) : "memory");
}
__device__ __forceinline__ void tma_load_2d(uint32_t smem_addr, const void* tmap,
                                            int32_t cx, int32_t cy, uint32_t mbar) {
    asm volatile(
        "cp.async.bulk.tensor.2d.shared::cta.global.tile.mbarrier::complete_tx::bytes "
        "[%0], [%1, {%2, %3}], [%4];"
        :: "r"(smem_addr), "l"(tmap), "r"(cx), "r"(cy), "r"(mbar) : "memory");
}

// ====================================================================
// Kernel 1: fused prep.  (unchanged from best config)
// ====================================================================
__global__ __launch_bounds__(256) void prep_kernel(
    const float* __restrict__ x, const float* __restrict__ nw,
    const float* __restrict__ nb,
    const float* __restrict__ qw, const float* __restrict__ kw,
    const float* __restrict__ vw, const float* __restrict__ qb,
    const float* __restrict__ kb, const float* __restrict__ vb)
{
    const int tid = threadIdx.x;

    if (blockIdx.x >= MROWS) {
        const int n = blockIdx.x - MROWS;
        const float* src;
        if (n < 2048) {
            src = qw + (size_t)n * KDIM;
            if (tid == 0) g_bias[n] = qb[n];
        } else if (n < 4096) {
            src = kw + (size_t)(n - 2048) * KDIM;
            if (tid == 0) g_bias[n] = kb[n - 2048];
        } else {
            src = vw + (size_t)(n - 4096) * KDIM;
            if (tid == 0) g_bias[n] = vb[n - 4096];
        }
        const float4* sr = reinterpret_cast<const float4*>(src);
        uint4* rowp = reinterpret_cast<uint4*>(g_W + (size_t)n * KDIM);
        const float4 a = sr[2 * tid];
        const float4 b = sr[2 * tid + 1];
        uint4 u;
        u.x = pack2h(a.x, a.y); u.y = pack2h(a.z, a.w);
        u.z = pack2h(b.x, b.y); u.w = pack2h(b.z, b.w);
        rowp[tid] = u;
        return;
    }

    const int row = blockIdx.x;
    const float4* xr = reinterpret_cast<const float4*>(x + (size_t)row * KDIM);

    float4 v0 = xr[2 * tid];
    float4 v1 = xr[2 * tid + 1];

    float s = v0.x + v0.y + v0.z + v0.w + v1.x + v1.y + v1.z + v1.w;
    float q = v0.x*v0.x + v0.y*v0.y + v0.z*v0.z + v0.w*v0.w +
              v1.x*v1.x + v1.y*v1.y + v1.z*v1.z + v1.w*v1.w;

    #pragma unroll
    for (int o = 16; o > 0; o >>= 1) {
        s += __shfl_xor_sync(0xffffffffu, s, o);
        q += __shfl_xor_sync(0xffffffffu, q, o);
    }

    __shared__ float red[2][8];
    __shared__ float mu_s, rs_s;
    const int wid = tid >> 5, lane = tid & 31;
    if (lane == 0) { red[0][wid] = s; red[1][wid] = q; }
    __syncthreads();
    if (tid == 0) {
        float ss = 0.f, qq = 0.f;
        #pragma unroll
        for (int i = 0; i < 8; i++) { ss += red[0][i]; qq += red[1][i]; }
        float mu  = ss * (1.0f / KDIM);
        float var = qq * (1.0f / KDIM) - mu * mu;
        mu_s = mu;
        rs_s = rsqrtf(var + LN_EPS);
    }
    __syncthreads();
    const float mu = mu_s, rs = rs_s;

    const float4* wr = reinterpret_cast<const float4*>(nw);
    const float4* br = reinterpret_cast<const float4*>(nb);
    uint4* rowp = reinterpret_cast<uint4*>(g_A + (size_t)row * KDIM);

    const float4 w0 = wr[2 * tid], w1 = wr[2 * tid + 1];
    const float4 b0 = br[2 * tid], b1 = br[2 * tid + 1];
    uint4 u;
    u.x = pack2h((v0.x - mu) * rs * w0.x + b0.x, (v0.y - mu) * rs * w0.y + b0.y);
    u.y = pack2h((v0.z - mu) * rs * w0.z + b0.z, (v0.w - mu) * rs * w0.w + b0.w);
    u.z = pack2h((v1.x - mu) * rs * w1.x + b1.x, (v1.y - mu) * rs * w1.y + b1.y);
    u.w = pack2h((v1.z - mu) * rs * w1.z + b1.z, (v1.w - mu) * rs * w1.w + b1.w);
    rowp[tid] = u;
}

// ====================================================================
// Kernel 2: fp16 mma.sync GEMM with TMA bulk-tensor loads.
//   R10 tile/warp config (128x128, 8 warps, 3 stages, 2 CTAs/SM) but
//   the cp.async burst (2048 LDGSTS/chunk) is replaced by 2 TMA loads
//   issued by one thread -> LSU freed for ldmatrix, tensor pipe fed.
// ====================================================================
__global__ __launch_bounds__(256, 2)
void qkv_gemm_kernel(float* __restrict__ out,
                     const __grid_constant__ CUtensorMap tmA,
                     const __grid_constant__ CUtensorMap tmB)
{
    extern __shared__ char smem[];
    __shared__ __align__(8) uint64_t mbars[NSTAGE];

    const int tid  = threadIdx.x;
    const int wid  = tid >> 5;
    const int lane = tid & 31;
    const int wm   = wid & 1;       // 0..1  (64 rows each)
    const int wn   = wid >> 1;      // 0..3  (32 cols each)
    // 1024-align stage base (TMA SW128 requires aligned tiles)
    const uint32_t sbase = (smem_u32(smem) + 1023u) & ~1023u;

    // tile mapping with group-of-8 m-tile swizzle for L2 reuse
    const int NT = NCOLS / BN;              // 48
    const int GM = 8;
    const int bid = blockIdx.x;
    const int grp = bid / (GM * NT);
    const int rem = bid % (GM * NT);
    const int mt_ = grp * GM + (rem % GM);
    const int nt_ = rem / GM;
    const int m0 = mt_ * BM;
    const int n0 = nt_ * BN;

    uint32_t mb[NSTAGE];
    #pragma unroll
    for (int i = 0; i < NSTAGE; i++) mb[i] = smem_u32(&mbars[i]);

    if (tid == 0) {
        #pragma unroll
        for (int i = 0; i < NSTAGE; i++) mbar_init(mb[i], 1);
    }
    __syncthreads();

    // prologue: chunks 0,1 into stages 0,1
    if (tid == 0) {
        mbar_expect_tx(mb[0], STAGE_BYTES);
        tma_load_2d(sbase,                 &tmA, 0,  m0, mb[0]);
        tma_load_2d(sbase + A_TILE_BYTES,  &tmB, 0,  n0, mb[0]);
        mbar_expect_tx(mb[1], STAGE_BYTES);
        tma_load_2d(sbase + STAGE_BYTES,                &tmA, BK, m0, mb[1]);
        tma_load_2d(sbase + STAGE_BYTES + A_TILE_BYTES, &tmB, BK, n0, mb[1]);
    }

    float acc[4][4][4];
    #pragma unroll
    for (int i = 0; i < 4; i++)
        #pragma unroll
        for (int j = 0; j < 4; j++)
            #pragma unroll
            for (int c = 0; c < 4; c++) acc[i][j][c] = 0.f;

    // precomputed lane pieces for ldmatrix addressing
    const int a_row_lane = lane & 15;                        // row within m16
    const int a_k_lane   = (lane >> 4) * 8;                  // k half
    const int b_row_lane = (lane & 7) + ((lane >> 4) << 3);  // row within n16
    const int b_k_lane   = ((lane >> 3) & 1) * 8;            // k half

    int sR = 0, phR = 0;      // read stage + parity
    int sW = 2;               // write stage = (kt+2) % 3

    #pragma unroll 1
    for (int kt = 0; kt < NKT; kt++) {
        // WAR: all warps finished reading stage sW (during kt-1) before TMA
        __syncthreads();
        if (tid == 0 && kt + 2 < NKT) {
            const uint32_t st = sbase + sW * STAGE_BYTES;
            mbar_expect_tx(mb[sW], STAGE_BYTES);
            tma_load_2d(st,                &tmA, (kt + 2) * BK, m0, mb[sW]);
            tma_load_2d(st + A_TILE_BYTES, &tmB, (kt + 2) * BK, n0, mb[sW]);
        }
        // wait for this iteration's chunk
        mbar_wait(mb[sR], phR);

        const uint32_t aBase = sbase + sR * STAGE_BYTES;
        const uint32_t bBase = aBase + A_TILE_BYTES;

        #pragma unroll
        for (int ks = 0; ks < 4; ks++) {
            const int k0 = ks * 16;
            // B fragments first
            uint32_t bf[4][2];
            #pragma unroll
            for (int p = 0; p < 2; p++) {
                const int rown = wn * 32 + p * 16 + b_row_lane;
                const uint32_t addr =
                    bBase + swz128((uint32_t)(rown * 128 + (k0 + b_k_lane) * 2));
                uint32_t r[4];
                ldsm_x4(addr, r);
                bf[2*p][0] = r[0]; bf[2*p][1] = r[1];
                bf[2*p+1][0] = r[2]; bf[2*p+1][1] = r[3];
            }
            uint32_t af[4][4];
            #pragma unroll
            for (int mt = 0; mt < 4; mt++) {
                const int row = wm * 64 + mt * 16 + a_row_lane;
                const uint32_t addr =
                    aBase + swz128((uint32_t)(row * 128 + (k0 + a_k_lane) * 2));
                ldsm_x4(addr, af[mt]);
            }
            #pragma unroll
            for (int mt = 0; mt < 4; mt++)
                #pragma unroll
                for (int nt = 0; nt < 4; nt++)
                    mma_f16(acc[mt][nt], af[mt], bf[nt][0], bf[nt][1]);
        }

        // rotate stages / parity
        if (++sR == NSTAGE) { sR = 0; phR ^= 1; }
        if (++sW == NSTAGE) { sW = 0; }
    }

    // epilogue: bias + direct stores (32B-sector aligned float2 per quad)
    const int gid = lane >> 2;       // 0..7 row within m8
    const int tq  = lane & 3;        // col pair
    float bb[4][2];
    #pragma unroll
    for (int nt = 0; nt < 4; nt++) {
        const int col = n0 + wn * 32 + nt * 8 + tq * 2;
        bb[nt][0] = g_bias[col];
        bb[nt][1] = g_bias[col + 1];
    }
    #pragma unroll
    for (int mt = 0; mt < 4; mt++) {
        const int row = m0 + wm * 64 + mt * 16 + gid;
        #pragma unroll
        for (int nt = 0; nt < 4; nt++) {
            const int col = n0 + wn * 32 + nt * 8 + tq * 2;
            float2 v0, v1;
            v0.x = acc[mt][nt][0] + bb[nt][0];
            v0.y = acc[mt][nt][1] + bb[nt][1];
            v1.x = acc[mt][nt][2] + bb[nt][0];
            v1.y = acc[mt][nt][3] + bb[nt][1];
            *reinterpret_cast<float2*>(out + (size_t)row * NCOLS + col) = v0;
            *reinterpret_cast<float2*>(out + (size_t)(row + 8) * NCOLS + col) = v1;
        }
    }
}

// ====================================================================
// launch (host code runs at capture time; no allocation, no sync)
// ====================================================================
typedef CUresult (*PFN_tmapEncode)(
    CUtensorMap*, CUtensorMapDataType, cuuint32_t, void*,
    const cuuint64_t*, const cuuint64_t*, const cuuint32_t*, const cuuint32_t*,
    CUtensorMapInterleave, CUtensorMapSwizzle, CUtensorMapL2promotion,
    CUtensorMapFloatOOBfill);

extern "C" void kernel_launch(void* const* d_in, const int* in_sizes, int n_in,
                              void* d_out, int out_size)
{
    const float* x  = (const float*)d_in[0];
    const float* nw = (const float*)d_in[1];
    const float* nb = (const float*)d_in[2];
    const float* qw = (const float*)d_in[3];
    const float* qb = (const float*)d_in[4];
    const float* kw = (const float*)d_in[5];
    const float* kb = (const float*)d_in[6];
    const float* vw = (const float*)d_in[7];
    const float* vb = (const float*)d_in[8];
    float* out = (float*)d_out;

    // driver entry point without linking libcuda
    void* fn = nullptr;
    cudaDriverEntryPointQueryResult qres;
    cudaGetDriverEntryPointByVersion("cuTensorMapEncodeTiled", &fn, 12000,
                                     cudaEnableDefault, &qres);
    PFN_tmapEncode encode = (PFN_tmapEncode)fn;

    void *pA = nullptr, *pW = nullptr;
    cudaGetSymbolAddress(&pA, g_A);
    cudaGetSymbolAddress(&pW, g_W);

    CUtensorMap tmA, tmB;
    {
        cuuint64_t dims[2]    = {KDIM, MROWS};
        cuuint64_t strides[1] = {KDIM * sizeof(__half)};
        cuuint32_t box[2]     = {BK, BM};          // 64 fp16 = 128B x 128 rows
        cuuint32_t estr[2]    = {1, 1};
        encode(&tmA, CU_TENSOR_MAP_DATA_TYPE_FLOAT16, 2, pA, dims, strides,
               box, estr, CU_TENSOR_MAP_INTERLEAVE_NONE,
               CU_TENSOR_MAP_SWIZZLE_128B, CU_TENSOR_MAP_L2_PROMOTION_L2_128B,
               CU_TENSOR_MAP_FLOAT_OOB_FILL_NONE);
    }
    {
        cuuint64_t dims[2]    = {KDIM, NCOLS};
        cuuint64_t strides[1] = {KDIM * sizeof(__half)};
        cuuint32_t box[2]     = {BK, BN};          // 64 fp16 x 128 rows
        cuuint32_t estr[2]    = {1, 1};
        encode(&tmB, CU_TENSOR_MAP_DATA_TYPE_FLOAT16, 2, pW, dims, strides,
               box, estr, CU_TENSOR_MAP_INTERLEAVE_NONE,
               CU_TENSOR_MAP_SWIZZLE_128B, CU_TENSOR_MAP_L2_PROMOTION_L2_128B,
               CU_TENSOR_MAP_FLOAT_OOB_FILL_NONE);
    }

    cudaFuncSetAttribute(qkv_gemm_kernel,
                         cudaFuncAttributeMaxDynamicSharedMemorySize, GEMM_SMEM);

    prep_kernel<<<MROWS + NCOLS, 256>>>(x, nw, nb, qw, kw, vw, qb, kb, vb);
    qkv_gemm_kernel<<<(MROWS / BM) * (NCOLS / BN), 256, GEMM_SMEM>>>(out, tmA, tmB);
}

// round 15
// speedup vs baseline: 1.0533x; 1.0108x over previous
#include <cuda_runtime.h>
#include <cuda_fp16.h>
#include <cuda.h>
#include <cstdint>

// ---------------- problem constants ----------------
#define MROWS 8192          // B*S = 4*2048
#define KDIM  2048
#define NCOLS 6144          // 3*D fused QKV
#define LN_EPS 1e-5f

// ---------------- GEMM tiling ----------------
#define BM 128
#define BN 128
#define BK 64
#define NKT (KDIM / BK)     // 32 k-chunks
#define NSTAGE 3

#define A_TILE_BYTES 16384          // 128 rows x 128B
#define B_TILE_BYTES 16384          // 128 rows x 128B
#define STAGE_BYTES  (A_TILE_BYTES + B_TILE_BYTES)   // 32768
#define GEMM_SMEM    (NSTAGE * STAGE_BYTES + 1024)   // +1024 for alignment

// ---------------- scratch (static device memory: allowed) ----------------
__device__ __half g_A[(size_t)MROWS * KDIM];   // 32 MB
__device__ __half g_W[(size_t)NCOLS * KDIM];   // 24 MB
__device__ float  g_bias[NCOLS];

// ---------------- helpers ----------------
__device__ __forceinline__ uint32_t smem_u32(const void* p) {
    return (uint32_t)__cvta_generic_to_shared(p);
}
__device__ __forceinline__ uint32_t swz128(uint32_t b) {
    return b ^ ((b >> 3) & 0x70);
}
__device__ __forceinline__ void ldsm_x4(uint32_t addr, uint32_t r[4]) {
    asm volatile("ldmatrix.sync.aligned.m8n8.x4.shared.b16 {%0,%1,%2,%3}, [%4];"
                 : "=r"(r[0]), "=r"(r[1]), "=r"(r[2]), "=r"(r[3]) : "r"(addr));
}
__device__ __forceinline__ void mma_f16(float c[4], const uint32_t a[4],
                                        const uint32_t b0, const uint32_t b1) {
    asm volatile(
        "mma.sync.aligned.m16n8k16.row.col.f32.f16.f16.f32 "
        "{%0,%1,%2,%3}, {%4,%5,%6,%7}, {%8,%9}, {%0,%1,%2,%3};"
        : "+f"(c[0]), "+f"(c[1]), "+f"(c[2]), "+f"(c[3])
        : "r"(a[0]), "r"(a[1]), "r"(a[2]), "r"(a[3]), "r"(b0), "r"(b1));
}
__device__ __forceinline__ uint32_t pack2h(float a, float b) {
    __half2 p = __halves2half2(__float2half_rn(a), __float2half_rn(b));
    return *reinterpret_cast<uint32_t*>(&p);
}
// ---- TMA / mbarrier (base sm_90 PTX features, not arch-conditional) ----
__device__ __forceinline__ void mbar_init(uint32_t mbar, uint32_t cnt) {
    asm volatile("mbarrier.init.shared.b64 [%0], %1;" :: "r"(mbar), "r"(cnt) : "memory");
}
__device__ __forceinline__ void mbar_expect_tx(uint32_t mbar, uint32_t bytes) {
    asm volatile("mbarrier.arrive.expect_tx.shared.b64 _, [%0], %1;"
                 :: "r"(mbar), "r"(bytes) : "memory");
}
__device__ __forceinline__ void mbar_arrive(uint32_t mbar) {
    asm volatile("mbarrier.arrive.shared.b64 _, [%0];" :: "r"(mbar) : "memory");
}
__device__ __forceinline__ void mbar_wait(uint32_t mbar, uint32_t parity) {
    asm volatile(
        "{\n\t.reg .pred P1;\n\t"
        "WAIT_%=:\n\t"
        "mbarrier.try_wait.parity.acquire.cta.shared::cta.b64 P1, [%0], %1, 0x989680;\n\t"
        "@P1 bra.uni DONE_%=;\n\t"
        "bra.uni WAIT_%=;\n\t"
        "DONE_%=:\n\t}"
        :: "r"(mbar), "r"(parity) : "memory");
}
__device__ __forceinline__ void tma_load_2d(uint32_t smem_addr, const void* tmap,
                                            int32_t cx, int32_t cy, uint32_t mbar) {
    asm volatile(
        "cp.async.bulk.tensor.2d.shared::cta.global.tile.mbarrier::complete_tx::bytes "
        "[%0], [%1, {%2, %3}], [%4];"
        :: "r"(smem_addr), "l"(tmap), "r"(cx), "r"(cy), "r"(mbar) : "memory");
}

// ====================================================================
// Kernel 1: fused prep.  (unchanged from best config)
// ====================================================================
__global__ __launch_bounds__(256) void prep_kernel(
    const float* __restrict__ x, const float* __restrict__ nw,
    const float* __restrict__ nb,
    const float* __restrict__ qw, const float* __restrict__ kw,
    const float* __restrict__ vw, const float* __restrict__ qb,
    const float* __restrict__ kb, const float* __restrict__ vb)
{
    const int tid = threadIdx.x;

    if (blockIdx.x >= MROWS) {
        const int n = blockIdx.x - MROWS;
        const float* src;
        if (n < 2048) {
            src = qw + (size_t)n * KDIM;
            if (tid == 0) g_bias[n] = qb[n];
        } else if (n < 4096) {
            src = kw + (size_t)(n - 2048) * KDIM;
            if (tid == 0) g_bias[n] = kb[n - 2048];
        } else {
            src = vw + (size_t)(n - 4096) * KDIM;
            if (tid == 0) g_bias[n] = vb[n - 4096];
        }
        const float4* sr = reinterpret_cast<const float4*>(src);
        uint4* rowp = reinterpret_cast<uint4*>(g_W + (size_t)n * KDIM);
        const float4 a = sr[2 * tid];
        const float4 b = sr[2 * tid + 1];
        uint4 u;
        u.x = pack2h(a.x, a.y); u.y = pack2h(a.z, a.w);
        u.z = pack2h(b.x, b.y); u.w = pack2h(b.z, b.w);
        rowp[tid] = u;
        return;
    }

    const int row = blockIdx.x;
    const float4* xr = reinterpret_cast<const float4*>(x + (size_t)row * KDIM);

    float4 v0 = xr[2 * tid];
    float4 v1 = xr[2 * tid + 1];

    float s = v0.x + v0.y + v0.z + v0.w + v1.x + v1.y + v1.z + v1.w;
    float q = v0.x*v0.x + v0.y*v0.y + v0.z*v0.z + v0.w*v0.w +
              v1.x*v1.x + v1.y*v1.y + v1.z*v1.z + v1.w*v1.w;

    #pragma unroll
    for (int o = 16; o > 0; o >>= 1) {
        s += __shfl_xor_sync(0xffffffffu, s, o);
        q += __shfl_xor_sync(0xffffffffu, q, o);
    }

    __shared__ float red[2][8];
    __shared__ float mu_s, rs_s;
    const int wid = tid >> 5, lane = tid & 31;
    if (lane == 0) { red[0][wid] = s; red[1][wid] = q; }
    __syncthreads();
    if (tid == 0) {
        float ss = 0.f, qq = 0.f;
        #pragma unroll
        for (int i = 0; i < 8; i++) { ss += red[0][i]; qq += red[1][i]; }
        float mu  = ss * (1.0f / KDIM);
        float var = qq * (1.0f / KDIM) - mu * mu;
        mu_s = mu;
        rs_s = rsqrtf(var + LN_EPS);
    }
    __syncthreads();
    const float mu = mu_s, rs = rs_s;

    const float4* wr = reinterpret_cast<const float4*>(nw);
    const float4* br = reinterpret_cast<const float4*>(nb);
    uint4* rowp = reinterpret_cast<uint4*>(g_A + (size_t)row * KDIM);

    const float4 w0 = wr[2 * tid], w1 = wr[2 * tid + 1];
    const float4 b0 = br[2 * tid], b1 = br[2 * tid + 1];
    uint4 u;
    u.x = pack2h((v0.x - mu) * rs * w0.x + b0.x, (v0.y - mu) * rs * w0.y + b0.y);
    u.y = pack2h((v0.z - mu) * rs * w0.z + b0.z, (v0.w - mu) * rs * w0.w + b0.w);
    u.z = pack2h((v1.x - mu) * rs * w1.x + b1.x, (v1.y - mu) * rs * w1.y + b1.y);
    u.w = pack2h((v1.z - mu) * rs * w1.z + b1.z, (v1.w - mu) * rs * w1.w + b1.w);
    rowp[tid] = u;
}

// ====================================================================
// Kernel 2: fp16 mma.sync GEMM, TMA loads + full producer/consumer
//   mbarrier pipeline.  NO block-wide barrier in the mainloop:
//   full[s] (count 1)  : TMA complete_tx -> consumer try_wait
//   empty[s] (count 8) : lane0-per-warp arrive after last ldsm of s;
//                        producer (tid 0) waits before reusing stage.
//   Warps drift up to a stage; skew feeds the tensor pipe.
// ====================================================================
__global__ __launch_bounds__(256, 2)
void qkv_gemm_kernel(float* __restrict__ out,
                     const __grid_constant__ CUtensorMap tmA,
                     const __grid_constant__ CUtensorMap tmB)
{
    extern __shared__ char smem[];
    __shared__ __align__(8) uint64_t mbF[NSTAGE];   // full barriers
    __shared__ __align__(8) uint64_t mbE[NSTAGE];   // empty barriers

    const int tid  = threadIdx.x;
    const int wid  = tid >> 5;
    const int lane = tid & 31;
    const int wm   = wid & 1;       // 0..1  (64 rows each)
    const int wn   = wid >> 1;      // 0..3  (32 cols each)
    // 1024-align stage base (TMA SW128 requires aligned tiles)
    const uint32_t sbase = (smem_u32(smem) + 1023u) & ~1023u;

    // tile mapping with group-of-8 m-tile swizzle for L2 reuse
    const int NT = NCOLS / BN;              // 48
    const int GM = 8;
    const int bid = blockIdx.x;
    const int grp = bid / (GM * NT);
    const int rem = bid % (GM * NT);
    const int mt_ = grp * GM + (rem % GM);
    const int nt_ = rem / GM;
    const int m0 = mt_ * BM;
    const int n0 = nt_ * BN;

    uint32_t fB[NSTAGE], eB[NSTAGE];
    #pragma unroll
    for (int i = 0; i < NSTAGE; i++) {
        fB[i] = smem_u32(&mbF[i]);
        eB[i] = smem_u32(&mbE[i]);
    }

    if (tid == 0) {
        #pragma unroll
        for (int i = 0; i < NSTAGE; i++) {
            mbar_init(fB[i], 1);     // completed by TMA complete_tx
            mbar_init(eB[i], 8);     // one arrive per warp
        }
    }
    __syncthreads();   // barriers visible before any TMA

    // prologue: producer fills stages 0,1 (first empty-waits pass: phase
    // convention — producer phase starts flipped on fresh barriers)
    if (tid == 0) {
        mbar_expect_tx(fB[0], STAGE_BYTES);
        tma_load_2d(sbase,                 &tmA, 0,  m0, fB[0]);
        tma_load_2d(sbase + A_TILE_BYTES,  &tmB, 0,  n0, fB[0]);
        mbar_expect_tx(fB[1], STAGE_BYTES);
        tma_load_2d(sbase + STAGE_BYTES,                &tmA, BK, m0, fB[1]);
        tma_load_2d(sbase + STAGE_BYTES + A_TILE_BYTES, &tmB, BK, n0, fB[1]);
    }

    float acc[4][4][4];
    #pragma unroll
    for (int i = 0; i < 4; i++)
        #pragma unroll
        for (int j = 0; j < 4; j++)
            #pragma unroll
            for (int c = 0; c < 4; c++) acc[i][j][c] = 0.f;

    // precomputed lane pieces for ldmatrix addressing
    const int a_row_lane = lane & 15;                        // row within m16
    const int a_k_lane   = (lane >> 4) * 8;                  // k half
    const int b_row_lane = (lane & 7) + ((lane >> 4) << 3);  // row within n16
    const int b_k_lane   = ((lane >> 3) & 1) * 8;            // k half

    int sR = 0, phR = 0;      // consumer cursor (full barriers)
    int sW = 2, phE = 1;      // producer cursor (empty barriers, phase flipped)

    #pragma unroll 1
    for (int kt = 0; kt < NKT; kt++) {
        // ---- producer: refill stage sW once its last reader arrived ----
        if (tid == 0 && kt + 2 < NKT) {
            mbar_wait(eB[sW], phE);                 // first passes immediately
            const uint32_t st = sbase + sW * STAGE_BYTES;
            mbar_expect_tx(fB[sW], STAGE_BYTES);
            tma_load_2d(st,                &tmA, (kt + 2) * BK, m0, fB[sW]);
            tma_load_2d(st + A_TILE_BYTES, &tmB, (kt + 2) * BK, n0, fB[sW]);
        }
        if (++sW == NSTAGE) { sW = 0; phE ^= 1; }

        // ---- consumer: wait for this stage's data ----
        mbar_wait(fB[sR], phR);

        const uint32_t aBase = sbase + sR * STAGE_BYTES;
        const uint32_t bBase = aBase + A_TILE_BYTES;

        #pragma unroll
        for (int ks = 0; ks < 4; ks++) {
            const int k0 = ks * 16;
            // B fragments first
            uint32_t bf[4][2];
            #pragma unroll
            for (int p = 0; p < 2; p++) {
                const int rown = wn * 32 + p * 16 + b_row_lane;
                const uint32_t addr =
                    bBase + swz128((uint32_t)(rown * 128 + (k0 + b_k_lane) * 2));
                uint32_t r[4];
                ldsm_x4(addr, r);
                bf[2*p][0] = r[0]; bf[2*p][1] = r[1];
                bf[2*p+1][0] = r[2]; bf[2*p+1][1] = r[3];
            }
            uint32_t af[4][4];
            #pragma unroll
            for (int mt = 0; mt < 4; mt++) {
                const int row = wm * 64 + mt * 16 + a_row_lane;
                const uint32_t addr =
                    aBase + swz128((uint32_t)(row * 128 + (k0 + a_k_lane) * 2));
                ldsm_x4(addr, af[mt]);
            }
            #pragma unroll
            for (int mt = 0; mt < 4; mt++)
                #pragma unroll
                for (int nt = 0; nt < 4; nt++)
                    mma_f16(acc[mt][nt], af[mt], bf[nt][0], bf[nt][1]);
        }

        // ---- consumer: this warp is done reading stage sR ----
        if (lane == 0) mbar_arrive(eB[sR]);
        if (++sR == NSTAGE) { sR = 0; phR ^= 1; }
    }

    // epilogue: bias + direct stores (32B-sector aligned float2 per quad)
    const int gid = lane >> 2;       // 0..7 row within m8
    const int tq  = lane & 3;        // col pair
    float bb[4][2];
    #pragma unroll
    for (int nt = 0; nt < 4; nt++) {
        const int col = n0 + wn * 32 + nt * 8 + tq * 2;
        bb[nt][0] = g_bias[col];
        bb[nt][1] = g_bias[col + 1];
    }
    #pragma unroll
    for (int mt = 0; mt < 4; mt++) {
        const int row = m0 + wm * 64 + mt * 16 + gid;
        #pragma unroll
        for (int nt = 0; nt < 4; nt++) {
            const int col = n0 + wn * 32 + nt * 8 + tq * 2;
            float2 v0, v1;
            v0.x = acc[mt][nt][0] + bb[nt][0];
            v0.y = acc[mt][nt][1] + bb[nt][1];
            v1.x = acc[mt][nt][2] + bb[nt][0];
            v1.y = acc[mt][nt][3] + bb[nt][1];
            *reinterpret_cast<float2*>(out + (size_t)row * NCOLS + col) = v0;
            *reinterpret_cast<float2*>(out + (size_t)(row + 8) * NCOLS + col) = v1;
        }
    }
}

// ====================================================================
// launch (host code runs at capture time; no allocation, no sync)
// ====================================================================
typedef CUresult (*PFN_tmapEncode)(
    CUtensorMap*, CUtensorMapDataType, cuuint32_t, void*,
    const cuuint64_t*, const cuuint64_t*, const cuuint32_t*, const cuuint32_t*,
    CUtensorMapInterleave, CUtensorMapSwizzle, CUtensorMapL2promotion,
    CUtensorMapFloatOOBfill);

extern "C" void kernel_launch(void* const* d_in, const int* in_sizes, int n_in,
                              void* d_out, int out_size)
{
    const float* x  = (const float*)d_in[0];
    const float* nw = (const float*)d_in[1];
    const float* nb = (const float*)d_in[2];
    const float* qw = (const float*)d_in[3];
    const float* qb = (const float*)d_in[4];
    const float* kw = (const float*)d_in[5];
    const float* kb = (const float*)d_in[6];
    const float* vw = (const float*)d_in[7];
    const float* vb = (const float*)d_in[8];
    float* out = (float*)d_out;

    // driver entry point without linking libcuda
    void* fn = nullptr;
    cudaDriverEntryPointQueryResult qres;
    cudaGetDriverEntryPointByVersion("cuTensorMapEncodeTiled", &fn, 12000,
                                     cudaEnableDefault, &qres);
    PFN_tmapEncode encode = (PFN_tmapEncode)fn;

    void *pA = nullptr, *pW = nullptr;
    cudaGetSymbolAddress(&pA, g_A);
    cudaGetSymbolAddress(&pW, g_W);

    CUtensorMap tmA, tmB;
    {
        cuuint64_t dims[2]    = {KDIM, MROWS};
        cuuint64_t strides[1] = {KDIM * sizeof(__half)};
        cuuint32_t box[2]     = {BK, BM};          // 64 fp16 = 128B x 128 rows
        cuuint32_t estr[2]    = {1, 1};
        encode(&tmA, CU_TENSOR_MAP_DATA_TYPE_FLOAT16, 2, pA, dims, strides,
               box, estr, CU_TENSOR_MAP_INTERLEAVE_NONE,
               CU_TENSOR_MAP_SWIZZLE_128B, CU_TENSOR_MAP_L2_PROMOTION_L2_128B,
               CU_TENSOR_MAP_FLOAT_OOB_FILL_NONE);
    }
    {
        cuuint64_t dims[2]    = {KDIM, NCOLS};
        cuuint64_t strides[1] = {KDIM * sizeof(__half)};
        cuuint32_t box[2]     = {BK, BN};          // 64 fp16 x 128 rows
        cuuint32_t estr[2]    = {1, 1};
        encode(&tmB, CU_TENSOR_MAP_DATA_TYPE_FLOAT16, 2, pW, dims, strides,
               box, estr, CU_TENSOR_MAP_INTERLEAVE_NONE,
               CU_TENSOR_MAP_SWIZZLE_128B, CU_TENSOR_MAP_L2_PROMOTION_L2_128B,
               CU_TENSOR_MAP_FLOAT_OOB_FILL_NONE);
    }

    cudaFuncSetAttribute(qkv_gemm_kernel,
                         cudaFuncAttributeMaxDynamicSharedMemorySize, GEMM_SMEM);

    prep_kernel<<<MROWS + NCOLS, 256>>>(x, nw, nb, qw, kw, vw, qb, kb, vb);
    qkv_gemm_kernel<<<(MROWS / BM) * (NCOLS / BN), 256, GEMM_SMEM>>>(out, tmA, tmB);
}